// round 5
// baseline (speedup 1.0000x reference)
#include <cuda_runtime.h>
#include <cuda_bf16.h>

#define TPB   256
#define NB    32   // batch
#define NG    20   // GT boxes per image
#define NLVL  5

struct LvlInfo {
    int aoff[NLVL + 1];  // anchor offsets per level (aoff[5] = total anchors)
    int boff[NLVL + 1];  // block offsets per level (boff[5] = total blocks in x)
};

// Scratch: packed (iou_bits << 32) | (0xFFFFFFFF - local_anchor_idx) per (b, lvl, g).
// Inverted index => atomicMax resolves exact-float ties to the SMALLEST anchor
// index, matching jnp.argmax first-wins semantics.
__device__ unsigned long long g_gtpack[NB * NLVL * NG];

__global__ void init_kernel() {
    int i = blockIdx.x * blockDim.x + threadIdx.x;
    if (i < NB * NLVL * NG) g_gtpack[i] = 0ull;
}

__device__ __forceinline__ const float* sel_anchor(int l,
    const float* a0, const float* a1, const float* a2, const float* a3, const float* a4) {
    switch (l) {
        case 0: return a0;
        case 1: return a1;
        case 2: return a2;
        case 3: return a3;
        default: return a4;
    }
}

__global__ __launch_bounds__(TPB) void main_kernel(
    const float* __restrict__ bb,   // (B, G, 4)
    const int*   __restrict__ ids,  // (B, G)
    const float* __restrict__ a0, const float* __restrict__ a1,
    const float* __restrict__ a2, const float* __restrict__ a3,
    const float* __restrict__ a4,
    float* __restrict__ out, LvlInfo L)
{
    __shared__ float sgx1[NG], sgy1[NG], sgx2[NG], sgy2[NG];
    __shared__ float sarea[NG], sid[NG];
    __shared__ unsigned long long red[TPB / 32];

    const int b   = blockIdx.y;
    const int tid = threadIdx.x;

    if (tid < NG) {
        float x1 = bb[(b * NG + tid) * 4 + 0];
        float y1 = bb[(b * NG + tid) * 4 + 1];
        float x2 = bb[(b * NG + tid) * 4 + 2];
        float y2 = bb[(b * NG + tid) * 4 + 3];
        sgx1[tid] = x1; sgy1[tid] = y1; sgx2[tid] = x2; sgy2[tid] = y2;
        sarea[tid] = (x2 - x1 + 1.0f) * (y2 - y1 + 1.0f);
        sid[tid]   = (float)ids[b * NG + tid];
    }
    __syncthreads();

    // Identify level of this block (blocks never span levels: counts 192/48/12/3/1).
    const int bx = blockIdx.x;
    int lvl = 0;
#pragma unroll
    for (int l = 1; l < NLVL; l++)
        if (bx >= L.boff[l]) lvl = l;

    const float* anch = sel_anchor(lvl, a0, a1, a2, a3, a4);
    const int local = (bx - L.boff[lvl]) * TPB + tid;
    const int nA    = L.aoff[lvl + 1] - L.aoff[lvl];
    const bool active = local < nA;

    float ax1 = 0.f, ay1 = 0.f, ax2 = 0.f, ay2 = 0.f, areaA = 1.f;
    if (active) {
        float4 av = *reinterpret_cast<const float4*>(anch + (size_t)local * 4);
        ax1 = av.x; ay1 = av.y; ax2 = av.z; ay2 = av.w;
        areaA = (ax2 - ax1 + 1.0f) * (ay2 - ay1 + 1.0f);
    }

    float best = -1.0f;
    int   bestg = 0;
    const int warp = tid >> 5, lane = tid & 31;

    for (int g = 0; g < NG; ++g) {
        unsigned long long pack = 0ull;
        if (active) {
            float iw = fminf(ax2, sgx2[g]) - fmaxf(ax1, sgx1[g]) + 1.0f;
            float ih = fminf(ay2, sgy2[g]) - fmaxf(ay1, sgy1[g]) + 1.0f;
            iw = fmaxf(iw, 0.0f);
            ih = fmaxf(ih, 0.0f);
            float inter = iw * ih;
            float iou = inter / (areaA + sarea[g] - inter);
            if (iou > best) { best = iou; bestg = g; }  // strict > => first-index tie win
            pack = ((unsigned long long)__float_as_uint(iou) << 32)
                 | (unsigned long long)(0xFFFFFFFFu - (unsigned)local);
        }
        // Block max-reduce of pack, then one global atomicMax per (block, g).
#pragma unroll
        for (int o = 16; o > 0; o >>= 1) {
            unsigned long long other = __shfl_down_sync(0xFFFFFFFFu, pack, o);
            if (other > pack) pack = other;
        }
        if (lane == 0) red[warp] = pack;
        __syncthreads();
        if (warp == 0) {
            unsigned long long p = (lane < TPB / 32) ? red[lane] : 0ull;
#pragma unroll
            for (int o = 4; o > 0; o >>= 1) {
                unsigned long long other = __shfl_down_sync(0xFFFFFFFFu, p, o);
                if (other > p) p = other;
            }
            if (lane == 0)
                atomicMax(&g_gtpack[(b * NLVL + lvl) * NG + g], p);
        }
        __syncthreads();
    }

    if (active) {
        const int Atot  = L.aoff[NLVL];
        const int aglob = L.aoff[lvl] + local;
        const bool pos    = best >= 0.5f;
        const bool ignore = best >= 0.4f;  // only checked if !pos
        float lab = pos ? sid[bestg] : (ignore ? -1.0f : 0.0f);
        out[(size_t)b * Atot + aglob] = lab;

        float4 r = make_float4(0.f, 0.f, 0.f, 0.f);
        if (pos) {
            float ew  = ax2 - ax1 + 1.0f;
            float eh  = ay2 - ay1 + 1.0f;
            float ecx = ax1 + 0.5f * ew;
            float ecy = ay1 + 0.5f * eh;
            float gw  = sgx2[bestg] - sgx1[bestg] + 1.0f;
            float gh  = sgy2[bestg] - sgy1[bestg] + 1.0f;
            float gcx = sgx1[bestg] + 0.5f * gw;
            float gcy = sgy1[bestg] + 0.5f * gh;
            r.x = (gcx - ecx) / ew;
            r.y = (gcy - ecy) / eh;
            r.z = logf(gw / ew);
            r.w = logf(gh / eh);
        }
        float* reg_base = out + (size_t)NB * Atot;
        reinterpret_cast<float4*>(reg_base)[(size_t)b * Atot + aglob] = r;
    }
}

// Forced positives: for each GT, the best-IoU anchor on the GT's best level is
// made positive and assigned that GT. One thread per batch; sequential over g
// (deterministic last-wins for duplicate anchors).
__global__ void fixup_kernel(
    const float* __restrict__ bb,
    const int*   __restrict__ ids,
    const float* __restrict__ a0, const float* __restrict__ a1,
    const float* __restrict__ a2, const float* __restrict__ a3,
    const float* __restrict__ a4,
    float* __restrict__ out, LvlInfo L)
{
    int b = threadIdx.x;
    if (b >= NB) return;
    const int Atot = L.aoff[NLVL];
    float* reg_base = out + (size_t)NB * Atot;

    for (int g = 0; g < NG; ++g) {
        // argmax over levels, first max wins (strict >, ascending level)
        float bestv = -1.0f;
        int bl = 0;
        unsigned long long bp = 0ull;
#pragma unroll
        for (int l = 0; l < NLVL; l++) {
            unsigned long long p = g_gtpack[(b * NLVL + l) * NG + g];
            float v = __uint_as_float((unsigned)(p >> 32));
            if (v > bestv) { bestv = v; bl = l; bp = p; }
        }
        int local = (int)(0xFFFFFFFFu - (unsigned)(bp & 0xFFFFFFFFull));
        int aglob = L.aoff[bl] + local;

        const float* anch = sel_anchor(bl, a0, a1, a2, a3, a4) + (size_t)local * 4;
        float ax1 = anch[0], ay1 = anch[1], ax2 = anch[2], ay2 = anch[3];

        float gx1 = bb[(b * NG + g) * 4 + 0];
        float gy1 = bb[(b * NG + g) * 4 + 1];
        float gx2 = bb[(b * NG + g) * 4 + 2];
        float gy2 = bb[(b * NG + g) * 4 + 3];

        out[(size_t)b * Atot + aglob] = (float)ids[b * NG + g];

        float ew  = ax2 - ax1 + 1.0f;
        float eh  = ay2 - ay1 + 1.0f;
        float ecx = ax1 + 0.5f * ew;
        float ecy = ay1 + 0.5f * eh;
        float gw  = gx2 - gx1 + 1.0f;
        float gh  = gy2 - gy1 + 1.0f;
        float gcx = gx1 + 0.5f * gw;
        float gcy = gy1 + 0.5f * gh;
        float4 r;
        r.x = (gcx - ecx) / ew;
        r.y = (gcy - ecy) / eh;
        r.z = logf(gw / ew);
        r.w = logf(gh / eh);
        reinterpret_cast<float4*>(reg_base)[(size_t)b * Atot + aglob] = r;
    }
}

extern "C" void kernel_launch(void* const* d_in, const int* in_sizes, int n_in,
                              void* d_out, int out_size) {
    const float* bb  = (const float*)d_in[0];
    const int*   ids = (const int*)d_in[1];
    const float* A[NLVL];
    LvlInfo L;
    L.aoff[0] = 0;
    L.boff[0] = 0;
    for (int l = 0; l < NLVL; l++) {
        A[l] = (const float*)d_in[2 + l];
        int nA = in_sizes[2 + l] / 4;
        L.aoff[l + 1] = L.aoff[l] + nA;
        L.boff[l + 1] = L.boff[l] + (nA + TPB - 1) / TPB;
    }
    float* out = (float*)d_out;

    init_kernel<<<(NB * NLVL * NG + 255) / 256, 256>>>();

    dim3 grid(L.boff[NLVL], NB);
    main_kernel<<<grid, TPB>>>(bb, ids, A[0], A[1], A[2], A[3], A[4], out, L);

    fixup_kernel<<<1, 32>>>(bb, ids, A[0], A[1], A[2], A[3], A[4], out, L);
}

// round 6
// speedup vs baseline: 1.6040x; 1.6040x over previous
#include <cuda_runtime.h>
#include <cuda_bf16.h>

#define TPB   256
#define NB    32   // batch
#define NG    20   // GT boxes per image
#define NLVL  5

struct LvlInfo {
    int aoff[NLVL + 1];  // anchor offsets per level (aoff[5] = total anchors)
    int boff[NLVL + 1];  // block offsets per level (boff[5] = total blocks in x)
};

// Scratch: packed (iou_bits << 32) | (0xFFFFFFFF - local_anchor_idx) per (b, lvl, g).
// Key = bit pattern of the *correctly rounded* IoU (non-negative float bits order
// like uints). Inverted index => atomicMax resolves exact ties to the SMALLEST
// anchor index, matching jnp.argmax first-wins semantics bit-exactly.
__device__ unsigned long long g_gtpack[NB * NLVL * NG];

__global__ void init_kernel() {
    int i = blockIdx.x * blockDim.x + threadIdx.x;
    if (i < NB * NLVL * NG) g_gtpack[i] = 0ull;
}

__device__ __forceinline__ const float* sel_anchor(int l,
    const float* a0, const float* a1, const float* a2, const float* a3, const float* a4) {
    switch (l) {
        case 0: return a0;
        case 1: return a1;
        case 2: return a2;
        case 3: return a3;
        default: return a4;
    }
}

__global__ __launch_bounds__(TPB) void main_kernel(
    const float* __restrict__ bb,   // (B, G, 4)
    const int*   __restrict__ ids,  // (B, G)
    const float* __restrict__ a0, const float* __restrict__ a1,
    const float* __restrict__ a2, const float* __restrict__ a3,
    const float* __restrict__ a4,
    float* __restrict__ out, LvlInfo L)
{
    __shared__ float4 sbox[NG];
    __shared__ float  sarea[NG], sid[NG];
    __shared__ unsigned long long spack[NG * TPB];   // 40 KB candidate tile

    const int b   = blockIdx.y;
    const int tid = threadIdx.x;

    if (tid < NG) {
        float4 g4 = reinterpret_cast<const float4*>(bb)[b * NG + tid];
        sbox[tid] = g4;
        // area_g = (x2-x0+1)*(y2-y1+1), rn-exact, no FMA contraction
        sarea[tid] = __fmul_rn(g4.z - g4.x + 1.0f, g4.w - g4.y + 1.0f);
        sid[tid]   = (float)ids[b * NG + tid];
    }
    __syncthreads();

    // Identify level of this block (blocks never span levels: 192/48/12/3/1).
    const int bx = blockIdx.x;
    int lvl = 0;
#pragma unroll
    for (int l = 1; l < NLVL; l++)
        if (bx >= L.boff[l]) lvl = l;

    const float* anch = sel_anchor(lvl, a0, a1, a2, a3, a4);
    const int local = (bx - L.boff[lvl]) * TPB + tid;
    const int nA    = L.aoff[lvl + 1] - L.aoff[lvl];
    const bool active = local < nA;

    float4 av = make_float4(0.f, 0.f, 0.f, 0.f);
    if (active) av = reinterpret_cast<const float4*>(anch)[local];
    const float areaA = __fmul_rn(av.z - av.x + 1.0f, av.w - av.y + 1.0f);
    const unsigned long long lowbits =
        (unsigned long long)(0xFFFFFFFFu - (unsigned)local);

    float best = -1.0f;
    int   bestg = 0;

#pragma unroll 4
    for (int g = 0; g < NG; ++g) {
        float4 gb = sbox[g];
        float iw = fminf(av.z, gb.z) - fmaxf(av.x, gb.x) + 1.0f;
        float ih = fminf(av.w, gb.w) - fmaxf(av.y, gb.y) + 1.0f;
        iw = fmaxf(iw, 0.0f);
        ih = fmaxf(ih, 0.0f);
        float inter = __fmul_rn(iw, ih);
        float denom = __fsub_rn(__fadd_rn(areaA, sarea[g]), inter);  // (aA+aG)-inter, rn
        float iou   = inter / denom;                                  // IEEE rn div
        if (iou > best) { best = iou; bestg = g; }                    // first-index wins
        unsigned long long pack = active
            ? (((unsigned long long)__float_as_uint(iou) << 32) | lowbits)
            : 0ull;
        spack[g * TPB + tid] = pack;
    }

    // Per-anchor outputs (independent of spack reads => issue before the barrier,
    // STGs drain while the block syncs).
    if (active) {
        const int Atot  = L.aoff[NLVL];
        const int aglob = L.aoff[lvl] + local;
        const bool pos    = best >= 0.5f;
        const bool ignore = best >= 0.4f;
        out[(size_t)b * Atot + aglob] = pos ? sid[bestg] : (ignore ? -1.0f : 0.0f);

        float4 r = make_float4(0.f, 0.f, 0.f, 0.f);
        if (pos) {
            float4 gb = sbox[bestg];
            float ew  = av.z - av.x + 1.0f;
            float eh  = av.w - av.y + 1.0f;
            float ecx = av.x + 0.5f * ew;
            float ecy = av.y + 0.5f * eh;
            float gw  = gb.z - gb.x + 1.0f;
            float gh  = gb.w - gb.y + 1.0f;
            float gcx = gb.x + 0.5f * gw;
            float gcy = gb.y + 0.5f * gh;
            r.x = (gcx - ecx) / ew;
            r.y = (gcy - ecy) / eh;
            r.z = logf(gw / ew);
            r.w = logf(gh / eh);
        }
        float* reg_base = out + (size_t)NB * Atot;
        reinterpret_cast<float4*>(reg_base)[(size_t)b * Atot + aglob] = r;
    }

    __syncthreads();

    // Transposed reduction: warp w reduces GT columns {w, w+8, w+16}.
    const int warp = tid >> 5, lane = tid & 31;
    for (int g = warp; g < NG; g += TPB / 32) {
        unsigned long long p = spack[g * TPB + lane];
#pragma unroll
        for (int k = 1; k < TPB / 32; k++) {
            unsigned long long q = spack[g * TPB + lane + 32 * k];
            if (q > p) p = q;
        }
#pragma unroll
        for (int o = 16; o > 0; o >>= 1) {
            unsigned long long q = __shfl_down_sync(0xFFFFFFFFu, p, o);
            if (q > p) p = q;
        }
        if (lane == 0)
            atomicMax(&g_gtpack[(b * NLVL + lvl) * NG + g], p);
    }
}

// Forced positives. Parallel compute (one thread per (b,g)), then a deterministic
// sequential store pass per batch (ascending g => last-wins on duplicate anchors,
// matching the previous passing round's semantics).
__global__ __launch_bounds__(NB * NG) void fixup_kernel(
    const float* __restrict__ bb,
    const int*   __restrict__ ids,
    const float* __restrict__ a0, const float* __restrict__ a1,
    const float* __restrict__ a2, const float* __restrict__ a3,
    const float* __restrict__ a4,
    float* __restrict__ out, LvlInfo L)
{
    __shared__ int    s_ag[NB * NG];
    __shared__ float  s_lab[NB * NG];
    __shared__ float4 s_reg[NB * NG];

    const int t = threadIdx.x;
    const int Atot = L.aoff[NLVL];

    if (t < NB * NG) {
        const int b = t / NG, g = t % NG;

        // argmax over levels of the per-level max IoU key; strict >, ascending
        // level => first max wins (bit-exact vs jnp.stack(...).argmax(axis=0)).
        float bestv = -1.0f;
        int bl = 0;
        unsigned long long bp = 0ull;
#pragma unroll
        for (int l = 0; l < NLVL; l++) {
            unsigned long long p = g_gtpack[(b * NLVL + l) * NG + g];
            float v = __uint_as_float((unsigned)(p >> 32));
            if (v > bestv) { bestv = v; bl = l; bp = p; }
        }
        int local = (int)(0xFFFFFFFFu - (unsigned)(bp & 0xFFFFFFFFull));
        int aglob = L.aoff[bl] + local;

        const float* ap = sel_anchor(bl, a0, a1, a2, a3, a4) + (size_t)local * 4;
        float ax1 = ap[0], ay1 = ap[1], ax2 = ap[2], ay2 = ap[3];

        float4 gb = reinterpret_cast<const float4*>(bb)[b * NG + g];

        float ew  = ax2 - ax1 + 1.0f;
        float eh  = ay2 - ay1 + 1.0f;
        float ecx = ax1 + 0.5f * ew;
        float ecy = ay1 + 0.5f * eh;
        float gw  = gb.z - gb.x + 1.0f;
        float gh  = gb.w - gb.y + 1.0f;
        float gcx = gb.x + 0.5f * gw;
        float gcy = gb.y + 0.5f * gh;
        float4 r;
        r.x = (gcx - ecx) / ew;
        r.y = (gcy - ecy) / eh;
        r.z = logf(gw / ew);
        r.w = logf(gh / eh);

        s_ag[t]  = aglob;
        s_lab[t] = (float)ids[b * NG + g];
        s_reg[t] = r;
    }
    __syncthreads();

    if (t < NB) {  // thread t = batch b; sequential over g => deterministic
        float* reg_base = out + (size_t)NB * Atot;
        for (int g = 0; g < NG; ++g) {
            int i = t * NG + g;
            int aglob = s_ag[i];
            out[(size_t)t * Atot + aglob] = s_lab[i];
            reinterpret_cast<float4*>(reg_base)[(size_t)t * Atot + aglob] = s_reg[i];
        }
    }
}

extern "C" void kernel_launch(void* const* d_in, const int* in_sizes, int n_in,
                              void* d_out, int out_size) {
    const float* bb  = (const float*)d_in[0];
    const int*   ids = (const int*)d_in[1];
    const float* A[NLVL];
    LvlInfo L;
    L.aoff[0] = 0;
    L.boff[0] = 0;
    for (int l = 0; l < NLVL; l++) {
        A[l] = (const float*)d_in[2 + l];
        int nA = in_sizes[2 + l] / 4;
        L.aoff[l + 1] = L.aoff[l] + nA;
        L.boff[l + 1] = L.boff[l] + (nA + TPB - 1) / TPB;
    }
    float* out = (float*)d_out;

    init_kernel<<<(NB * NLVL * NG + 255) / 256, 256>>>();

    dim3 grid(L.boff[NLVL], NB);
    main_kernel<<<grid, TPB>>>(bb, ids, A[0], A[1], A[2], A[3], A[4], out, L);

    fixup_kernel<<<1, NB * NG>>>(bb, ids, A[0], A[1], A[2], A[3], A[4], out, L);
}

// round 7
// speedup vs baseline: 2.8509x; 1.7774x over previous
#include <cuda_runtime.h>
#include <cuda_bf16.h>

#define TPB   256
#define APT   2            // anchors per thread
#define NB    32           // batch
#define NG    20           // GT boxes per image
#define NLVL  5

struct LvlInfo {
    int aoff[NLVL + 1];  // anchor offsets per level (aoff[5] = total anchors)
    int boff[NLVL + 1];  // block offsets per level (boff[5] = total x-blocks)
};

// Scratch: packed (iou_bits << 32) | (0xFFFFFFFF - local_anchor_idx) per (b,lvl,g).
// IoU >= 0 so its float bits order like uints. Inverted index => atomicMax
// resolves exact-bit ties to the SMALLEST anchor index (jnp.argmax first-wins).
// Zero-initialized at module load; fixup_kernel re-zeroes it after consuming,
// so every kernel_launch call sees it zeroed (no init kernel needed).
__device__ unsigned long long g_gtpack[NB * NLVL * NG];

// Correctly-rounded fp32 division, branch-free (Markstein fast path).
// Valid for normal positive d, |result| in normal range — always true here.
// Bit-identical to IEEE div.rn.f32 on these operands.
__device__ __forceinline__ float div_rn_fast(float n, float d) {
    float r;
    asm("rcp.approx.ftz.f32 %0, %1;" : "=f"(r) : "f"(d));
    float e  = __fmaf_rn(-d, r, 1.0f);
    r        = __fmaf_rn(e, r, r);          // refined reciprocal (<1 ulp)
    float q  = __fmul_rn(n, r);
    float e2 = __fmaf_rn(-d, q, n);
    return __fmaf_rn(e2, r, q);             // correctly rounded quotient
}

__device__ __forceinline__ const float* sel_anchor(int l,
    const float* a0, const float* a1, const float* a2, const float* a3, const float* a4) {
    switch (l) {
        case 0: return a0;
        case 1: return a1;
        case 2: return a2;
        case 3: return a3;
        default: return a4;
    }
}

__global__ __launch_bounds__(TPB) void main_kernel(
    const float* __restrict__ bb,   // (B, G, 4)
    const int*   __restrict__ ids,  // (B, G)
    const float* __restrict__ a0, const float* __restrict__ a1,
    const float* __restrict__ a2, const float* __restrict__ a3,
    const float* __restrict__ a4,
    float* __restrict__ out, LvlInfo L)
{
    __shared__ float4 sbox[NG];
    __shared__ float  sarea[NG], sid[NG];
    __shared__ unsigned long long spack[NG * TPB];   // 40 KB candidate tile

    const int b   = blockIdx.y;
    const int tid = threadIdx.x;

    if (tid < NG) {
        float4 g4 = reinterpret_cast<const float4*>(bb)[b * NG + tid];
        sbox[tid] = g4;
        sarea[tid] = __fmul_rn(g4.z - g4.x + 1.0f, g4.w - g4.y + 1.0f);
        sid[tid]   = (float)ids[b * NG + tid];
    }
    __syncthreads();

    // Level of this block (blocks never span levels: 96/24/6/2/1).
    const int bx = blockIdx.x;
    int lvl = 0;
#pragma unroll
    for (int l = 1; l < NLVL; l++)
        if (bx >= L.boff[l]) lvl = l;

    const float* anch = sel_anchor(lvl, a0, a1, a2, a3, a4);
    const int base = (bx - L.boff[lvl]) * (TPB * APT) + tid;
    const int nA   = L.aoff[lvl + 1] - L.aoff[lvl];

    float4   av[APT];
    float    areaA[APT];
    unsigned lowb[APT];
    bool     act[APT];
    float    best[APT];
    int      bestg[APT];

#pragma unroll
    for (int k = 0; k < APT; k++) {
        int local = base + k * TPB;
        act[k]   = local < nA;
        av[k]    = make_float4(0.f, 0.f, 0.f, 0.f);
        if (act[k]) av[k] = reinterpret_cast<const float4*>(anch)[local];
        areaA[k] = __fmul_rn(av[k].z - av[k].x + 1.0f, av[k].w - av[k].y + 1.0f);
        lowb[k]  = 0xFFFFFFFFu - (unsigned)local;
        best[k]  = -1.0f;
        bestg[k] = 0;
    }

#pragma unroll 2
    for (int g = 0; g < NG; ++g) {
        float4 gb = sbox[g];
        float  sag = sarea[g];
        unsigned long long pm = 0ull;
#pragma unroll
        for (int k = 0; k < APT; k++) {
            float iw = fminf(av[k].z, gb.z) - fmaxf(av[k].x, gb.x) + 1.0f;
            float ih = fminf(av[k].w, gb.w) - fmaxf(av[k].y, gb.y) + 1.0f;
            iw = fmaxf(iw, 0.0f);
            ih = fmaxf(ih, 0.0f);
            float inter = __fmul_rn(iw, ih);
            float denom = __fsub_rn(__fadd_rn(areaA[k], sag), inter);
            float iou   = div_rn_fast(inter, denom);      // == IEEE rn div bits
            if (iou > best[k]) { best[k] = iou; bestg[k] = g; }  // first-idx wins
            unsigned long long pack = act[k]
                ? (((unsigned long long)__float_as_uint(iou) << 32)
                   | (unsigned long long)lowb[k])
                : 0ull;
            if (pack > pm) pm = pack;   // local merge; ~idx keeps first-wins ties
        }
        spack[g * TPB + tid] = pm;
    }

    // Per-anchor outputs (independent of spack reads => STGs drain under barrier).
    const int Atot = L.aoff[NLVL];
    float* reg_base = out + (size_t)NB * Atot;
#pragma unroll
    for (int k = 0; k < APT; k++) {
        if (!act[k]) continue;
        const int aglob = L.aoff[lvl] + base + k * TPB;
        const bool pos    = best[k] >= 0.5f;
        const bool ignore = best[k] >= 0.4f;
        out[(size_t)b * Atot + aglob] = pos ? sid[bestg[k]] : (ignore ? -1.0f : 0.0f);

        float4 r = make_float4(0.f, 0.f, 0.f, 0.f);
        if (pos) {
            float4 gb = sbox[bestg[k]];
            float ew  = av[k].z - av[k].x + 1.0f;
            float eh  = av[k].w - av[k].y + 1.0f;
            float ecx = av[k].x + 0.5f * ew;
            float ecy = av[k].y + 0.5f * eh;
            float gw  = gb.z - gb.x + 1.0f;
            float gh  = gb.w - gb.y + 1.0f;
            float gcx = gb.x + 0.5f * gw;
            float gcy = gb.y + 0.5f * gh;
            r.x = div_rn_fast(gcx - ecx, ew);
            r.y = div_rn_fast(gcy - ecy, eh);
            r.z = logf(div_rn_fast(gw, ew));
            r.w = logf(div_rn_fast(gh, eh));
        }
        reinterpret_cast<float4*>(reg_base)[(size_t)b * Atot + aglob] = r;
    }

    __syncthreads();

    // Transposed reduction: warp w reduces GT columns {w, w+8, w+16}.
    const int warp = tid >> 5, lane = tid & 31;
    for (int g = warp; g < NG; g += TPB / 32) {
        unsigned long long p = spack[g * TPB + lane];
#pragma unroll
        for (int k = 1; k < TPB / 32; k++) {
            unsigned long long q = spack[g * TPB + lane + 32 * k];
            if (q > p) p = q;
        }
#pragma unroll
        for (int o = 16; o > 0; o >>= 1) {
            unsigned long long q = __shfl_down_sync(0xFFFFFFFFu, p, o);
            if (q > p) p = q;
        }
        if (lane == 0)
            atomicMax(&g_gtpack[(b * NLVL + lvl) * NG + g], p);
    }
}

// Forced positives: parallel compute (one thread per (b,g)), deterministic
// sequential store pass per batch (ascending g => last-wins on duplicates).
// Then re-zeroes g_gtpack so the next launch starts clean.
__global__ __launch_bounds__(NB * NG) void fixup_kernel(
    const float* __restrict__ bb,
    const int*   __restrict__ ids,
    const float* __restrict__ a0, const float* __restrict__ a1,
    const float* __restrict__ a2, const float* __restrict__ a3,
    const float* __restrict__ a4,
    float* __restrict__ out, LvlInfo L)
{
    __shared__ int    s_ag[NB * NG];
    __shared__ float  s_lab[NB * NG];
    __shared__ float4 s_reg[NB * NG];

    const int t = threadIdx.x;
    const int Atot = L.aoff[NLVL];

    if (t < NB * NG) {
        const int b = t / NG, g = t % NG;

        // argmax over levels; strict >, ascending level => first max wins
        // (bit-exact vs jnp.stack(...).argmax(axis=0)).
        float bestv = -1.0f;
        int bl = 0;
        unsigned long long bp = 0ull;
#pragma unroll
        for (int l = 0; l < NLVL; l++) {
            unsigned long long p = g_gtpack[(b * NLVL + l) * NG + g];
            float v = __uint_as_float((unsigned)(p >> 32));
            if (v > bestv) { bestv = v; bl = l; bp = p; }
        }
        int local = (int)(0xFFFFFFFFu - (unsigned)(bp & 0xFFFFFFFFull));
        int aglob = L.aoff[bl] + local;

        const float* ap = sel_anchor(bl, a0, a1, a2, a3, a4) + (size_t)local * 4;
        float ax1 = ap[0], ay1 = ap[1], ax2 = ap[2], ay2 = ap[3];

        float4 gb = reinterpret_cast<const float4*>(bb)[b * NG + g];

        float ew  = ax2 - ax1 + 1.0f;
        float eh  = ay2 - ay1 + 1.0f;
        float ecx = ax1 + 0.5f * ew;
        float ecy = ay1 + 0.5f * eh;
        float gw  = gb.z - gb.x + 1.0f;
        float gh  = gb.w - gb.y + 1.0f;
        float gcx = gb.x + 0.5f * gw;
        float gcy = gb.y + 0.5f * gh;
        float4 r;
        r.x = div_rn_fast(gcx - ecx, ew);
        r.y = div_rn_fast(gcy - ecy, eh);
        r.z = logf(div_rn_fast(gw, ew));
        r.w = logf(div_rn_fast(gh, eh));

        s_ag[t]  = aglob;
        s_lab[t] = (float)ids[b * NG + g];
        s_reg[t] = r;
    }
    __syncthreads();

    if (t < NB) {  // thread t = batch b; sequential over g => deterministic
        float* reg_base = out + (size_t)NB * Atot;
        for (int g = 0; g < NG; ++g) {
            int i = t * NG + g;
            int aglob = s_ag[i];
            out[(size_t)t * Atot + aglob] = s_lab[i];
            reinterpret_cast<float4*>(reg_base)[(size_t)t * Atot + aglob] = s_reg[i];
        }
    }

    // Leave scratch zeroed for the next launch (replaces init_kernel).
    for (int i = t; i < NB * NLVL * NG; i += NB * NG)
        g_gtpack[i] = 0ull;
}

extern "C" void kernel_launch(void* const* d_in, const int* in_sizes, int n_in,
                              void* d_out, int out_size) {
    const float* bb  = (const float*)d_in[0];
    const int*   ids = (const int*)d_in[1];
    const float* A[NLVL];
    LvlInfo L;
    L.aoff[0] = 0;
    L.boff[0] = 0;
    for (int l = 0; l < NLVL; l++) {
        A[l] = (const float*)d_in[2 + l];
        int nA = in_sizes[2 + l] / 4;
        L.aoff[l + 1] = L.aoff[l] + nA;
        L.boff[l + 1] = L.boff[l] + (nA + TPB * APT - 1) / (TPB * APT);
    }
    float* out = (float*)d_out;

    dim3 grid(L.boff[NLVL], NB);
    main_kernel<<<grid, TPB>>>(bb, ids, A[0], A[1], A[2], A[3], A[4], out, L);

    fixup_kernel<<<1, NB * NG>>>(bb, ids, A[0], A[1], A[2], A[3], A[4], out, L);
}

// round 8
// speedup vs baseline: 3.5092x; 1.2309x over previous
#include <cuda_runtime.h>
#include <cuda_bf16.h>

#define TPB   256
#define APT   2            // anchors per thread
#define NB    32           // batch
#define NG    20           // GT boxes per image
#define NLVL  5

struct LvlInfo {
    int aoff[NLVL + 1];  // anchor offsets per level (aoff[5] = total anchors)
    int boff[NLVL + 1];  // block offsets per level (boff[5] = total x-blocks)
};

// Scratch: packed (iou_bits << 32) | (0xFFFFFFFF - local_anchor_idx) per (b,lvl,g).
// IoU >= 0 so its float bits order like uints. Inverted index => atomicMax
// resolves exact-bit ties to the SMALLEST anchor index (jnp.argmax first-wins).
// Zero at module load; the fixup phase re-zeroes after consuming, so every
// launch (incl. graph replays) starts clean.
__device__ unsigned long long g_gtpack[NB * NLVL * NG];
__device__ int g_done;   // last-block-done counter, reset each launch

// Correctly-rounded fp32 division, branch-free (Markstein fast path).
// Valid for normal positive d with in-range quotient — always true here.
// Bit-identical to IEEE div.rn.f32 on these operands.
__device__ __forceinline__ float div_rn_fast(float n, float d) {
    float r;
    asm("rcp.approx.ftz.f32 %0, %1;" : "=f"(r) : "f"(d));
    float e  = __fmaf_rn(-d, r, 1.0f);
    r        = __fmaf_rn(e, r, r);
    float q  = __fmul_rn(n, r);
    float e2 = __fmaf_rn(-d, q, n);
    return __fmaf_rn(e2, r, q);
}

__device__ __forceinline__ const float* sel_anchor(int l,
    const float* a0, const float* a1, const float* a2, const float* a3, const float* a4) {
    switch (l) {
        case 0: return a0;
        case 1: return a1;
        case 2: return a2;
        case 3: return a3;
        default: return a4;
    }
}

__global__ __launch_bounds__(TPB) void main_kernel(
    const float* __restrict__ bb,   // (B, G, 4)
    const int*   __restrict__ ids,  // (B, G)
    const float* __restrict__ a0, const float* __restrict__ a1,
    const float* __restrict__ a2, const float* __restrict__ a3,
    const float* __restrict__ a4,
    float* __restrict__ out, LvlInfo L)
{
    __shared__ float4 sbox[NG];
    __shared__ float  sarea[NG], sid[NG];
    __shared__ __align__(16) unsigned long long spack[NG * TPB];  // 40 KB tile
    __shared__ int s_last;

    const int b   = blockIdx.y;
    const int tid = threadIdx.x;

    if (tid < NG) {
        float4 g4 = reinterpret_cast<const float4*>(bb)[b * NG + tid];
        sbox[tid]  = g4;
        sarea[tid] = __fmul_rn(g4.z - g4.x + 1.0f, g4.w - g4.y + 1.0f);
        sid[tid]   = (float)ids[b * NG + tid];
    }
    __syncthreads();

    // Level of this block (blocks never span levels: 96/24/6/2/1).
    const int bx = blockIdx.x;
    int lvl = 0;
#pragma unroll
    for (int l = 1; l < NLVL; l++)
        if (bx >= L.boff[l]) lvl = l;

    const float* anch = sel_anchor(lvl, a0, a1, a2, a3, a4);
    const int base = (bx - L.boff[lvl]) * (TPB * APT) + tid;
    const int nA   = L.aoff[lvl + 1] - L.aoff[lvl];

    float4   av[APT];
    float    areaA[APT];
    unsigned lowb[APT];
    bool     act[APT];
    float    best[APT];
    int      bestg[APT];

#pragma unroll
    for (int k = 0; k < APT; k++) {
        int local = base + k * TPB;
        act[k] = local < nA;
        // Inactive sentinel: far-away box => iw < 0 for every GT => fully pruned.
        av[k]  = make_float4(4e9f, 4e9f, 4e9f, 4e9f);
        if (act[k]) av[k] = reinterpret_cast<const float4*>(anch)[local];
        areaA[k] = __fmul_rn(av[k].z - av[k].x + 1.0f, av[k].w - av[k].y + 1.0f);
        lowb[k]  = 0xFFFFFFFFu - (unsigned)local;
        best[k]  = 0.0f;   // IoU >= 0; zero-overlap pairs never update => argmax
        bestg[k] = 0;      // of an all-zero row is g=0, matching jnp.argmax.
    }

#pragma unroll 2
    for (int g = 0; g < NG; ++g) {
        float4 gb  = sbox[g];
        float  sag = sarea[g];
        unsigned long long pm = 0ull;
#pragma unroll
        for (int k = 0; k < APT; k++) {
            float iw = fminf(av[k].z, gb.z) - fmaxf(av[k].x, gb.x) + 1.0f;
            float ih = fminf(av[k].w, gb.w) - fmaxf(av[k].y, gb.y) + 1.0f;
            if (iw > 0.0f && ih > 0.0f) {   // ~85% of pairs skip (coherent branch)
                float inter = __fmul_rn(iw, ih);
                float denom = __fsub_rn(__fadd_rn(areaA[k], sag), inter);
                float iou   = div_rn_fast(inter, denom);   // == IEEE rn div bits
                if (iou > best[k]) { best[k] = iou; bestg[k] = g; }
                unsigned long long pack =
                    ((unsigned long long)__float_as_uint(iou) << 32)
                    | (unsigned long long)lowb[k];
                if (pack > pm) pm = pack;   // ~idx => smaller anchor idx wins ties
            }
        }
        spack[g * TPB + tid] = pm;
    }

    // Per-anchor outputs (independent of spack reads => STGs drain under barrier).
    const int Atot = L.aoff[NLVL];
    float* reg_base = out + (size_t)NB * Atot;
#pragma unroll
    for (int k = 0; k < APT; k++) {
        if (!act[k]) continue;
        const int aglob = L.aoff[lvl] + base + k * TPB;
        const bool pos    = best[k] >= 0.5f;
        const bool ignore = best[k] >= 0.4f;
        out[(size_t)b * Atot + aglob] = pos ? sid[bestg[k]] : (ignore ? -1.0f : 0.0f);

        float4 r = make_float4(0.f, 0.f, 0.f, 0.f);
        if (pos) {
            float4 gb = sbox[bestg[k]];
            float ew  = av[k].z - av[k].x + 1.0f;
            float eh  = av[k].w - av[k].y + 1.0f;
            float ecx = av[k].x + 0.5f * ew;
            float ecy = av[k].y + 0.5f * eh;
            float gw  = gb.z - gb.x + 1.0f;
            float gh  = gb.w - gb.y + 1.0f;
            float gcx = gb.x + 0.5f * gw;
            float gcy = gb.y + 0.5f * gh;
            r.x = div_rn_fast(gcx - ecx, ew);
            r.y = div_rn_fast(gcy - ecy, eh);
            r.z = logf(div_rn_fast(gw, ew));
            r.w = logf(div_rn_fast(gh, eh));
        }
        reinterpret_cast<float4*>(reg_base)[(size_t)b * Atot + aglob] = r;
    }

    __syncthreads();

    // Transposed reduction: warp w reduces GT columns {w, w+8, w+16}.
    const int warp = tid >> 5, lane = tid & 31;
    for (int g = warp; g < NG; g += TPB / 32) {
        unsigned long long p = spack[g * TPB + lane];
#pragma unroll
        for (int k = 1; k < TPB / 32; k++) {
            unsigned long long q = spack[g * TPB + lane + 32 * k];
            if (q > p) p = q;
        }
#pragma unroll
        for (int o = 16; o > 0; o >>= 1) {
            unsigned long long q = __shfl_down_sync(0xFFFFFFFFu, p, o);
            if (q > p) p = q;
        }
        if (lane == 0)
            atomicMax(&g_gtpack[(b * NLVL + lvl) * NG + g], p);
    }

    // ── Last-block-done: the final block runs the forced-positive fixup ──
    __syncthreads();
    if (tid == 0) {
        __threadfence();   // release: our out[] stores + gtpack atomics
        int n = atomicAdd(&g_done, 1);
        s_last = (n == (int)(gridDim.x * gridDim.y) - 1);
    }
    __syncthreads();
    if (!s_last) return;
    __threadfence();       // acquire: see every block's stores/atomics

    // Stage fixup results in the (now free) spack tile.
    int*    s_ag  = reinterpret_cast<int*>(spack);
    float*  s_lab = reinterpret_cast<float*>(s_ag + NB * NG);
    float4* s_reg = reinterpret_cast<float4*>(s_lab + NB * NG);  // +5120B, 16-aligned

    for (int t = tid; t < NB * NG; t += TPB) {
        const int bb_i = t / NG, g = t % NG;

        // argmax over levels; strict >, ascending => first max wins
        // (bit-exact vs jnp.stack(...).argmax(axis=0)).
        float bestv = -1.0f;
        int bl = 0;
        unsigned long long bp = 0ull;
#pragma unroll
        for (int l = 0; l < NLVL; l++) {
            unsigned long long p = g_gtpack[(bb_i * NLVL + l) * NG + g];
            float v = __uint_as_float((unsigned)(p >> 32));
            if (v > bestv) { bestv = v; bl = l; bp = p; }
        }
        int local = (int)(0xFFFFFFFFu - (unsigned)(bp & 0xFFFFFFFFull));
        int aglob = L.aoff[bl] + local;

        const float* ap = sel_anchor(bl, a0, a1, a2, a3, a4) + (size_t)local * 4;
        float ax1 = ap[0], ay1 = ap[1], ax2 = ap[2], ay2 = ap[3];
        float4 gb = reinterpret_cast<const float4*>(bb)[bb_i * NG + g];

        float ew  = ax2 - ax1 + 1.0f;
        float eh  = ay2 - ay1 + 1.0f;
        float ecx = ax1 + 0.5f * ew;
        float ecy = ay1 + 0.5f * eh;
        float gw  = gb.z - gb.x + 1.0f;
        float gh  = gb.w - gb.y + 1.0f;
        float gcx = gb.x + 0.5f * gw;
        float gcy = gb.y + 0.5f * gh;
        float4 r;
        r.x = div_rn_fast(gcx - ecx, ew);
        r.y = div_rn_fast(gcy - ecy, eh);
        r.z = logf(div_rn_fast(gw, ew));
        r.w = logf(div_rn_fast(gh, eh));

        s_ag[t]  = aglob;
        s_lab[t] = (float)ids[bb_i * NG + g];
        s_reg[t] = r;
    }
    __syncthreads();

    if (tid < NB) {  // thread = batch; ascending g => deterministic last-wins
        for (int g = 0; g < NG; ++g) {
            int i = tid * NG + g;
            int aglob = s_ag[i];
            out[(size_t)tid * Atot + aglob] = s_lab[i];
            reinterpret_cast<float4*>(reg_base)[(size_t)tid * Atot + aglob] = s_reg[i];
        }
    }

    // Reset scratch for the next launch / graph replay.
    if (tid == 0) g_done = 0;
    for (int i = tid; i < NB * NLVL * NG; i += TPB)
        g_gtpack[i] = 0ull;
}

extern "C" void kernel_launch(void* const* d_in, const int* in_sizes, int n_in,
                              void* d_out, int out_size) {
    const float* bb  = (const float*)d_in[0];
    const int*   ids = (const int*)d_in[1];
    const float* A[NLVL];
    LvlInfo L;
    L.aoff[0] = 0;
    L.boff[0] = 0;
    for (int l = 0; l < NLVL; l++) {
        A[l] = (const float*)d_in[2 + l];
        int nA = in_sizes[2 + l] / 4;
        L.aoff[l + 1] = L.aoff[l] + nA;
        L.boff[l + 1] = L.boff[l] + (nA + TPB * APT - 1) / (TPB * APT);
    }
    float* out = (float*)d_out;

    dim3 grid(L.boff[NLVL], NB);
    main_kernel<<<grid, TPB>>>(bb, ids, A[0], A[1], A[2], A[3], A[4], out, L);
}

// round 9
// speedup vs baseline: 3.8197x; 1.0885x over previous
#include <cuda_runtime.h>
#include <cuda_bf16.h>

#define TPB   256
#define APT   2            // anchors per thread
#define NB    32           // batch
#define NG    20           // GT boxes per image
#define NLVL  5

struct LvlInfo {
    int aoff[NLVL + 1];
    int boff[NLVL + 1];
};

// Packed (iou_bits << 32) | (0xFFFFFFFF - local_anchor_idx) per (b,lvl,g).
// IoU >= 0 => float bits order as uints; inverted idx => atomicMax ties to the
// SMALLEST anchor index (jnp.argmax first-wins). Zero at load; fixup re-zeroes.
__device__ unsigned long long g_gtpack[NB * NLVL * NG];
__device__ int g_done;

// Correctly-rounded fp32 division, branch-free (Markstein fast path).
// Bit-identical to IEEE div.rn.f32 for the operands seen here.
__device__ __forceinline__ float div_rn_fast(float n, float d) {
    float r;
    asm("rcp.approx.ftz.f32 %0, %1;" : "=f"(r) : "f"(d));
    float e  = __fmaf_rn(-d, r, 1.0f);
    r        = __fmaf_rn(e, r, r);
    float q  = __fmul_rn(n, r);
    float e2 = __fmaf_rn(-d, q, n);
    return __fmaf_rn(e2, r, q);
}

__device__ __forceinline__ const float* sel_anchor(int l,
    const float* a0, const float* a1, const float* a2, const float* a3, const float* a4) {
    switch (l) {
        case 0: return a0;
        case 1: return a1;
        case 2: return a2;
        case 3: return a3;
        default: return a4;
    }
}

__global__ __launch_bounds__(TPB) void main_kernel(
    const float* __restrict__ bb,   // (B, G, 4)
    const int*   __restrict__ ids,  // (B, G)
    const float* __restrict__ a0, const float* __restrict__ a1,
    const float* __restrict__ a2, const float* __restrict__ a3,
    const float* __restrict__ a4,
    float* __restrict__ out, LvlInfo L)
{
    __shared__ float4 sbox[NG];
    __shared__ float  sarea[NG], sid[NG];
    __shared__ __align__(16) unsigned long long spack[NG * TPB];  // 40 KB tile
    __shared__ float4 sbbx[TPB / 32];   // per-warp anchor bbox partials
    __shared__ int s_last;

    const int b   = blockIdx.y;
    const int tid = threadIdx.x;
    const int warp = tid >> 5, lane = tid & 31;

    if (tid < NG) {
        float4 g4 = reinterpret_cast<const float4*>(bb)[b * NG + tid];
        sbox[tid]  = g4;
        sarea[tid] = __fmul_rn(g4.z - g4.x + 1.0f, g4.w - g4.y + 1.0f);
        sid[tid]   = (float)ids[b * NG + tid];
    }

    // Level of this block (blocks never span levels: 96/24/6/2/1).
    const int bx = blockIdx.x;
    int lvl = 0;
#pragma unroll
    for (int l = 1; l < NLVL; l++)
        if (bx >= L.boff[l]) lvl = l;

    const float* anch = sel_anchor(lvl, a0, a1, a2, a3, a4);
    const int base = (bx - L.boff[lvl]) * (TPB * APT) + tid;
    const int nA   = L.aoff[lvl + 1] - L.aoff[lvl];

    float4   av[APT];
    float    areaA[APT];
    unsigned lowb[APT];
    bool     act[APT];
    float    best[APT];
    int      bestg[APT];

    // Thread-local anchor bbox (inactive anchors excluded via +/-inf).
    float tx1 = __int_as_float(0x7F800000), ty1 = tx1;   // +inf
    float tx2 = -tx1, ty2 = -tx1;                        // -inf

#pragma unroll
    for (int k = 0; k < APT; k++) {
        int local = base + k * TPB;
        act[k] = local < nA;
        av[k]  = make_float4(4e9f, 4e9f, 4e9f, 4e9f);   // sentinel: never overlaps
        if (act[k]) {
            av[k] = reinterpret_cast<const float4*>(anch)[local];
            tx1 = fminf(tx1, av[k].x); ty1 = fminf(ty1, av[k].y);
            tx2 = fmaxf(tx2, av[k].z); ty2 = fmaxf(ty2, av[k].w);
        }
        areaA[k] = __fmul_rn(av[k].z - av[k].x + 1.0f, av[k].w - av[k].y + 1.0f);
        lowb[k]  = 0xFFFFFFFFu - (unsigned)local;
        best[k]  = 0.0f;   // zero-overlap rows => argmax g=0, matching jnp
        bestg[k] = 0;
    }

    // Warp-level bbox reduce.
#pragma unroll
    for (int o = 16; o > 0; o >>= 1) {
        tx1 = fminf(tx1, __shfl_xor_sync(0xFFFFFFFFu, tx1, o));
        ty1 = fminf(ty1, __shfl_xor_sync(0xFFFFFFFFu, ty1, o));
        tx2 = fmaxf(tx2, __shfl_xor_sync(0xFFFFFFFFu, tx2, o));
        ty2 = fmaxf(ty2, __shfl_xor_sync(0xFFFFFFFFu, ty2, o));
    }
    if (lane == 0) sbbx[warp] = make_float4(tx1, ty1, tx2, ty2);

    // Pre-zero this thread's 20 tile slots (its only writers).
#pragma unroll
    for (int g = 0; g < NG; ++g) spack[g * TPB + tid] = 0ull;

    __syncthreads();

    // Finish block bbox (every thread; 8 entries).
    float bx1 = sbbx[0].x, by1 = sbbx[0].y, bx2 = sbbx[0].z, by2 = sbbx[0].w;
#pragma unroll
    for (int w = 1; w < TPB / 32; w++) {
        float4 v = sbbx[w];
        bx1 = fminf(bx1, v.x); by1 = fminf(by1, v.y);
        bx2 = fmaxf(bx2, v.z); by2 = fmaxf(by2, v.w);
    }

#pragma unroll 2
    for (int g = 0; g < NG; ++g) {
        float4 gb = sbox[g];
        // Block-uniform skip: can ANY anchor in this block overlap GT g?
        float bw = fminf(bx2, gb.z) - fmaxf(bx1, gb.x) + 1.0f;
        float bh = fminf(by2, gb.w) - fmaxf(by1, gb.y) + 1.0f;
        if (bw > 0.0f && bh > 0.0f) {
            float sag = sarea[g];
            float    pv  = 0.0f;
            unsigned plo = 0u;
#pragma unroll
            for (int k = 0; k < APT; k++) {
                float iw = fminf(av[k].z, gb.z) - fmaxf(av[k].x, gb.x) + 1.0f;
                float ih = fminf(av[k].w, gb.w) - fmaxf(av[k].y, gb.y) + 1.0f;
                if (iw > 0.0f && ih > 0.0f) {
                    float inter = __fmul_rn(iw, ih);
                    float denom = __fsub_rn(__fadd_rn(areaA[k], sag), inter);
                    float iou   = div_rn_fast(inter, denom);   // == IEEE rn div
                    if (iou > best[k]) { best[k] = iou; bestg[k] = g; }
                    // strict > : tie keeps k=0 (larger lowb = smaller idx) — same
                    // as the u64 max semantics.
                    if (iou > pv) { pv = iou; plo = lowb[k]; }
                }
            }
            if (pv > 0.0f)
                spack[g * TPB + tid] =
                    ((unsigned long long)__float_as_uint(pv) << 32)
                    | (unsigned long long)plo;
        }
    }

    // Per-anchor outputs (STGs drain under the coming barrier).
    const int Atot = L.aoff[NLVL];
    float* reg_base = out + (size_t)NB * Atot;
#pragma unroll
    for (int k = 0; k < APT; k++) {
        if (!act[k]) continue;
        const int aglob = L.aoff[lvl] + base + k * TPB;
        const bool pos    = best[k] >= 0.5f;
        const bool ignore = best[k] >= 0.4f;
        out[(size_t)b * Atot + aglob] = pos ? sid[bestg[k]] : (ignore ? -1.0f : 0.0f);

        float4 r = make_float4(0.f, 0.f, 0.f, 0.f);
        if (pos) {
            float4 gb = sbox[bestg[k]];
            float ew  = av[k].z - av[k].x + 1.0f;
            float eh  = av[k].w - av[k].y + 1.0f;
            float ecx = av[k].x + 0.5f * ew;
            float ecy = av[k].y + 0.5f * eh;
            float gw  = gb.z - gb.x + 1.0f;
            float gh  = gb.w - gb.y + 1.0f;
            float gcx = gb.x + 0.5f * gw;
            float gcy = gb.y + 0.5f * gh;
            r.x = div_rn_fast(gcx - ecx, ew);
            r.y = div_rn_fast(gcy - ecy, eh);
            r.z = logf(div_rn_fast(gw, ew));
            r.w = logf(div_rn_fast(gh, eh));
        }
        reinterpret_cast<float4*>(reg_base)[(size_t)b * Atot + aglob] = r;
    }

    __syncthreads();

    // Transposed per-GT reduction, u32 two-phase with zero-column early-out.
    // Phase 1: max of hi words (iou bits). Phase 2 (only if nonzero): max of lo
    // among hi==maxhi (lo = ~idx => max lo = min anchor idx). Exactly the u64 max.
    for (int g = warp; g < NG; g += TPB / 32) {
        uint2 v[TPB / 32];
#pragma unroll
        for (int k = 0; k < TPB / 32; k++)
            v[k] = reinterpret_cast<const uint2*>(spack)[g * TPB + lane + 32 * k];

        unsigned hi = v[0].y;
#pragma unroll
        for (int k = 1; k < TPB / 32; k++) hi = max(hi, v[k].y);
#pragma unroll
        for (int o = 16; o > 0; o >>= 1)
            hi = max(hi, __shfl_xor_sync(0xFFFFFFFFu, hi, o));   // all lanes get max

        if (hi != 0u) {   // warp-uniform
            unsigned lo = 0u;
#pragma unroll
            for (int k = 0; k < TPB / 32; k++)
                if (v[k].y == hi) lo = max(lo, v[k].x);
#pragma unroll
            for (int o = 16; o > 0; o >>= 1)
                lo = max(lo, __shfl_xor_sync(0xFFFFFFFFu, lo, o));
            if (lane == 0)
                atomicMax(&g_gtpack[(b * NLVL + lvl) * NG + g],
                          ((unsigned long long)hi << 32) | (unsigned long long)lo);
        }
    }

    // ── Last-block-done: final block applies forced positives ──
    __syncthreads();
    if (tid == 0) {
        __threadfence();
        int n = atomicAdd(&g_done, 1);
        s_last = (n == (int)(gridDim.x * gridDim.y) - 1);
    }
    __syncthreads();
    if (!s_last) return;
    __threadfence();

    int*    s_ag  = reinterpret_cast<int*>(spack);
    float*  s_lab = reinterpret_cast<float*>(s_ag + NB * NG);
    float4* s_reg = reinterpret_cast<float4*>(s_lab + NB * NG);

    for (int t = tid; t < NB * NG; t += TPB) {
        const int bb_i = t / NG, g = t % NG;

        float bestv = -1.0f;
        int bl = 0;
        unsigned long long bp = 0ull;
#pragma unroll
        for (int l = 0; l < NLVL; l++) {
            unsigned long long p = g_gtpack[(bb_i * NLVL + l) * NG + g];
            float v = __uint_as_float((unsigned)(p >> 32));
            if (v > bestv) { bestv = v; bl = l; bp = p; }   // first max wins
        }
        int local = (int)(0xFFFFFFFFu - (unsigned)(bp & 0xFFFFFFFFull));
        int aglob = L.aoff[bl] + local;

        const float* ap = sel_anchor(bl, a0, a1, a2, a3, a4) + (size_t)local * 4;
        float ax1 = ap[0], ay1 = ap[1], ax2 = ap[2], ay2 = ap[3];
        float4 gb = reinterpret_cast<const float4*>(bb)[bb_i * NG + g];

        float ew  = ax2 - ax1 + 1.0f;
        float eh  = ay2 - ay1 + 1.0f;
        float ecx = ax1 + 0.5f * ew;
        float ecy = ay1 + 0.5f * eh;
        float gw  = gb.z - gb.x + 1.0f;
        float gh  = gb.w - gb.y + 1.0f;
        float gcx = gb.x + 0.5f * gw;
        float gcy = gb.y + 0.5f * gh;
        float4 r;
        r.x = div_rn_fast(gcx - ecx, ew);
        r.y = div_rn_fast(gcy - ecy, eh);
        r.z = logf(div_rn_fast(gw, ew));
        r.w = logf(div_rn_fast(gh, eh));

        s_ag[t]  = aglob;
        s_lab[t] = (float)ids[bb_i * NG + g];
        s_reg[t] = r;
    }
    __syncthreads();

    if (tid < NB) {  // thread = batch; ascending g => deterministic last-wins
        for (int g = 0; g < NG; ++g) {
            int i = tid * NG + g;
            int aglob = s_ag[i];
            out[(size_t)tid * Atot + aglob] = s_lab[i];
            reinterpret_cast<float4*>(reg_base)[(size_t)tid * Atot + aglob] = s_reg[i];
        }
    }

    if (tid == 0) g_done = 0;
    for (int i = tid; i < NB * NLVL * NG; i += TPB)
        g_gtpack[i] = 0ull;
}

extern "C" void kernel_launch(void* const* d_in, const int* in_sizes, int n_in,
                              void* d_out, int out_size) {
    const float* bb  = (const float*)d_in[0];
    const int*   ids = (const int*)d_in[1];
    const float* A[NLVL];
    LvlInfo L;
    L.aoff[0] = 0;
    L.boff[0] = 0;
    for (int l = 0; l < NLVL; l++) {
        A[l] = (const float*)d_in[2 + l];
        int nA = in_sizes[2 + l] / 4;
        L.aoff[l + 1] = L.aoff[l] + nA;
        L.boff[l + 1] = L.boff[l] + (nA + TPB * APT - 1) / (TPB * APT);
    }
    float* out = (float*)d_out;

    dim3 grid(L.boff[NLVL], NB);
    main_kernel<<<grid, TPB>>>(bb, ids, A[0], A[1], A[2], A[3], A[4], out, L);
}

// round 10
// speedup vs baseline: 4.1659x; 1.0906x over previous
#include <cuda_runtime.h>
#include <cuda_bf16.h>

#define TPB   256
#define APT   2            // anchors per thread (ADJACENT pair: 2t, 2t+1)
#define NB    32           // batch
#define NG    20           // GT boxes per image
#define NLVL  5

struct LvlInfo {
    int aoff[NLVL + 1];
    int boff[NLVL + 1];
};

// Packed (iou_bits << 32) | (0xFFFFFFFF - local_anchor_idx) per (b,lvl,g).
// IoU >= 0 => float bits order as uints; inverted idx => atomicMax ties to the
// SMALLEST anchor index (jnp.argmax first-wins). Zero at load; last block
// re-zeroes after consuming, so graph replays start clean.
__device__ unsigned long long g_gtpack[NB * NLVL * NG];
__device__ int g_done;

// Correctly-rounded fp32 division, branch-free (Markstein fast path).
// Bit-identical to IEEE div.rn.f32 for the operands seen here.
__device__ __forceinline__ float div_rn_fast(float n, float d) {
    float r;
    asm("rcp.approx.ftz.f32 %0, %1;" : "=f"(r) : "f"(d));
    float e  = __fmaf_rn(-d, r, 1.0f);
    r        = __fmaf_rn(e, r, r);
    float q  = __fmul_rn(n, r);
    float e2 = __fmaf_rn(-d, q, n);
    return __fmaf_rn(e2, r, q);
}

__device__ __forceinline__ const float* sel_anchor(int l,
    const float* a0, const float* a1, const float* a2, const float* a3, const float* a4) {
    switch (l) {
        case 0: return a0;
        case 1: return a1;
        case 2: return a2;
        case 3: return a3;
        default: return a4;
    }
}

__global__ __launch_bounds__(TPB) void main_kernel(
    const float* __restrict__ bb,   // (B, G, 4)
    const int*   __restrict__ ids,  // (B, G)
    const float* __restrict__ a0, const float* __restrict__ a1,
    const float* __restrict__ a2, const float* __restrict__ a3,
    const float* __restrict__ a4,
    float* __restrict__ out, LvlInfo L)
{
    __shared__ float4 sbox[NG];
    __shared__ float  sarea[NG], sid[NG];
    __shared__ int    s_last;
    // Fixup staging (used only by the last block; ~15.4 KB).
    __shared__ int    s_ag[NB * NG];
    __shared__ float  s_lab[NB * NG];
    __shared__ __align__(16) float4 s_reg[NB * NG];

    const int b    = blockIdx.y;
    const int tid  = threadIdx.x;
    const int lane = tid & 31;

    if (tid < NG) {
        float4 g4 = reinterpret_cast<const float4*>(bb)[b * NG + tid];
        sbox[tid]  = g4;
        sarea[tid] = __fmul_rn(g4.z - g4.x + 1.0f, g4.w - g4.y + 1.0f);
        sid[tid]   = (float)ids[b * NG + tid];
    }

    // Level of this block (blocks never span levels: 96/24/6/2/1).
    const int bx = blockIdx.x;
    int lvl = 0;
#pragma unroll
    for (int l = 1; l < NLVL; l++)
        if (bx >= L.boff[l]) lvl = l;

    const float* anch = sel_anchor(lvl, a0, a1, a2, a3, a4);
    const int nA = L.aoff[lvl + 1] - L.aoff[lvl];
    // ADJACENT pair: thread owns anchors base+0, base+1 => warp owns 64
    // consecutive anchors => tight warp bbox for pruning.
    const int base = ((bx - L.boff[lvl]) * TPB + tid) * APT;

    float4   av[APT];
    float    areaA[APT];
    unsigned lowb[APT];
    bool     act[APT];
    float    best[APT];
    int      bestg[APT];

    const float INF = __int_as_float(0x7F800000);
    float tx1 = INF, ty1 = INF, tx2 = -INF, ty2 = -INF;

#pragma unroll
    for (int k = 0; k < APT; k++) {
        int local = base + k;
        act[k] = local < nA;
        av[k]  = make_float4(4e9f, 4e9f, 4e9f, 4e9f);   // sentinel: never overlaps
        if (act[k]) {
            av[k] = reinterpret_cast<const float4*>(anch)[local];
            tx1 = fminf(tx1, av[k].x); ty1 = fminf(ty1, av[k].y);
            tx2 = fmaxf(tx2, av[k].z); ty2 = fmaxf(ty2, av[k].w);
        }
        areaA[k] = __fmul_rn(av[k].z - av[k].x + 1.0f, av[k].w - av[k].y + 1.0f);
        lowb[k]  = 0xFFFFFFFFu - (unsigned)local;
        best[k]  = 0.0f;   // zero-overlap rows => argmax g=0, matching jnp
        bestg[k] = 0;
    }

    // Warp bbox (all lanes end with the full warp reduction via xor pattern).
#pragma unroll
    for (int o = 16; o > 0; o >>= 1) {
        tx1 = fminf(tx1, __shfl_xor_sync(0xFFFFFFFFu, tx1, o));
        ty1 = fminf(ty1, __shfl_xor_sync(0xFFFFFFFFu, ty1, o));
        tx2 = fmaxf(tx2, __shfl_xor_sync(0xFFFFFFFFu, tx2, o));
        ty2 = fmaxf(ty2, __shfl_xor_sync(0xFFFFFFFFu, ty2, o));
    }
    // Conservative overlap bounds: GT overlaps some anchor in this warp only if
    // gb.z >= tx1-1 && gb.x <= tx2+1 && gb.w >= ty1-1 && gb.y <= ty2+1.
    // (+/-1 exact for coords < 2^23; all-inactive warps get inf bounds => never pass.)
    const float wx1 = tx1 - 1.0f, wx2 = tx2 + 1.0f;
    const float wy1 = ty1 - 1.0f, wy2 = ty2 + 1.0f;

    __syncthreads();

    const unsigned long long gbase = (unsigned long long)(b * NLVL + lvl) * NG;

    for (int g = 0; g < NG; ++g) {
        float4 gb = sbox[g];
        // Warp-uniform prune (bounds identical across lanes).
        if (gb.z >= wx1 && gb.x <= wx2 && gb.w >= wy1 && gb.y <= wy2) {
            float sag = sarea[g];
            float    pv  = 0.0f;
            unsigned plo = 0u;
#pragma unroll
            for (int k = 0; k < APT; k++) {
                float iw = fminf(av[k].z, gb.z) - fmaxf(av[k].x, gb.x) + 1.0f;
                float ih = fminf(av[k].w, gb.w) - fmaxf(av[k].y, gb.y) + 1.0f;
                if (iw > 0.0f && ih > 0.0f) {
                    float inter = __fmul_rn(iw, ih);
                    float denom = __fsub_rn(__fadd_rn(areaA[k], sag), inter);
                    float iou   = div_rn_fast(inter, denom);   // == IEEE rn div
                    if (iou > best[k]) { best[k] = iou; bestg[k] = g; }
                    // strict >: tie keeps k=0 (smaller idx) — matches u64-max.
                    if (iou > pv) { pv = iou; plo = lowb[k]; }
                }
            }
            // Warp reduction via REDUX: max iou bits, then min idx among ties.
            unsigned hv = __float_as_uint(pv);
            unsigned mh = __reduce_max_sync(0xFFFFFFFFu, hv);
            if (mh != 0u) {   // warp-uniform
                unsigned lo = (hv == mh) ? plo : 0u;
                unsigned ml = __reduce_max_sync(0xFFFFFFFFu, lo);
                if (lane == 0)
                    atomicMax(&g_gtpack[gbase + g],
                              ((unsigned long long)mh << 32) | (unsigned long long)ml);
            }
        }
    }

    // Per-anchor outputs.
    const int Atot = L.aoff[NLVL];
    float* reg_base = out + (size_t)NB * Atot;
#pragma unroll
    for (int k = 0; k < APT; k++) {
        if (!act[k]) continue;
        const int aglob = L.aoff[lvl] + base + k;
        const bool pos    = best[k] >= 0.5f;
        const bool ignore = best[k] >= 0.4f;
        out[(size_t)b * Atot + aglob] = pos ? sid[bestg[k]] : (ignore ? -1.0f : 0.0f);

        float4 r = make_float4(0.f, 0.f, 0.f, 0.f);
        if (pos) {
            float4 gb = sbox[bestg[k]];
            float ew  = av[k].z - av[k].x + 1.0f;
            float eh  = av[k].w - av[k].y + 1.0f;
            float ecx = av[k].x + 0.5f * ew;
            float ecy = av[k].y + 0.5f * eh;
            float gw  = gb.z - gb.x + 1.0f;
            float gh  = gb.w - gb.y + 1.0f;
            float gcx = gb.x + 0.5f * gw;
            float gcy = gb.y + 0.5f * gh;
            r.x = div_rn_fast(gcx - ecx, ew);
            r.y = div_rn_fast(gcy - ecy, eh);
            r.z = logf(div_rn_fast(gw, ew));
            r.w = logf(div_rn_fast(gh, eh));
        }
        reinterpret_cast<float4*>(reg_base)[(size_t)b * Atot + aglob] = r;
    }

    // ── Last-block-done: final block applies forced positives ──
    __syncthreads();
    if (tid == 0) {
        __threadfence();
        int n = atomicAdd(&g_done, 1);
        s_last = (n == (int)(gridDim.x * gridDim.y) - 1);
    }
    __syncthreads();
    if (!s_last) return;
    __threadfence();

    for (int t = tid; t < NB * NG; t += TPB) {
        const int bb_i = t / NG, g = t % NG;

        // argmax over levels; strict >, ascending => first max wins
        // (bit-exact vs jnp.stack(...).argmax(axis=0)).
        float bestv = -1.0f;
        int bl = 0;
        unsigned long long bp = 0ull;
#pragma unroll
        for (int l = 0; l < NLVL; l++) {
            unsigned long long p = g_gtpack[(bb_i * NLVL + l) * NG + g];
            float v = __uint_as_float((unsigned)(p >> 32));
            if (v > bestv) { bestv = v; bl = l; bp = p; }
        }
        int local = (int)(0xFFFFFFFFu - (unsigned)(bp & 0xFFFFFFFFull));
        int aglob = L.aoff[bl] + local;

        const float* ap = sel_anchor(bl, a0, a1, a2, a3, a4) + (size_t)local * 4;
        float ax1 = ap[0], ay1 = ap[1], ax2 = ap[2], ay2 = ap[3];
        float4 gb = reinterpret_cast<const float4*>(bb)[bb_i * NG + g];

        float ew  = ax2 - ax1 + 1.0f;
        float eh  = ay2 - ay1 + 1.0f;
        float ecx = ax1 + 0.5f * ew;
        float ecy = ay1 + 0.5f * eh;
        float gw  = gb.z - gb.x + 1.0f;
        float gh  = gb.w - gb.y + 1.0f;
        float gcx = gb.x + 0.5f * gw;
        float gcy = gb.y + 0.5f * gh;
        float4 r;
        r.x = div_rn_fast(gcx - ecx, ew);
        r.y = div_rn_fast(gcy - ecy, eh);
        r.z = logf(div_rn_fast(gw, ew));
        r.w = logf(div_rn_fast(gh, eh));

        s_ag[t]  = aglob;
        s_lab[t] = (float)ids[bb_i * NG + g];
        s_reg[t] = r;
    }
    __syncthreads();

    if (tid < NB) {  // thread = batch; ascending g => deterministic last-wins
        for (int g = 0; g < NG; ++g) {
            int i = tid * NG + g;
            int aglob = s_ag[i];
            out[(size_t)tid * Atot + aglob] = s_lab[i];
            reinterpret_cast<float4*>(reg_base)[(size_t)tid * Atot + aglob] = s_reg[i];
        }
    }

    // Reset scratch for the next launch / graph replay.
    if (tid == 0) g_done = 0;
    for (int i = tid; i < NB * NLVL * NG; i += TPB)
        g_gtpack[i] = 0ull;
}

extern "C" void kernel_launch(void* const* d_in, const int* in_sizes, int n_in,
                              void* d_out, int out_size) {
    const float* bb  = (const float*)d_in[0];
    const int*   ids = (const int*)d_in[1];
    const float* A[NLVL];
    LvlInfo L;
    L.aoff[0] = 0;
    L.boff[0] = 0;
    for (int l = 0; l < NLVL; l++) {
        A[l] = (const float*)d_in[2 + l];
        int nA = in_sizes[2 + l] / 4;
        L.aoff[l + 1] = L.aoff[l] + nA;
        L.boff[l + 1] = L.boff[l] + (nA + TPB * APT - 1) / (TPB * APT);
    }
    float* out = (float*)d_out;

    dim3 grid(L.boff[NLVL], NB);
    main_kernel<<<grid, TPB>>>(bb, ids, A[0], A[1], A[2], A[3], A[4], out, L);
}

// round 11
// speedup vs baseline: 4.6296x; 1.1113x over previous
#include <cuda_runtime.h>
#include <cuda_bf16.h>

#define TPB   256
#define APT   2            // anchors per thread (ADJACENT pair: 2t, 2t+1)
#define NB    32           // batch
#define NG    20           // GT boxes per image
#define NLVL  5

struct LvlInfo {
    int aoff[NLVL + 1];
    int boff[NLVL + 1];
};

// Packed (iou_bits << 32) | (0xFFFFFFFF - local_anchor_idx) per (b,lvl,g).
// IoU >= 0 => float bits order as uints; inverted idx => atomicMax ties to the
// SMALLEST anchor index (jnp.argmax first-wins). Zero at load; last block
// re-zeroes after consuming, so graph replays start clean.
__device__ unsigned long long g_gtpack[NB * NLVL * NG];
__device__ int g_done;

// Correctly-rounded fp32 division, branch-free (Markstein fast path).
// Bit-identical to IEEE div.rn.f32 for the operands seen here.
__device__ __forceinline__ float div_rn_fast(float n, float d) {
    float r;
    asm("rcp.approx.ftz.f32 %0, %1;" : "=f"(r) : "f"(d));
    float e  = __fmaf_rn(-d, r, 1.0f);
    r        = __fmaf_rn(e, r, r);
    float q  = __fmul_rn(n, r);
    float e2 = __fmaf_rn(-d, q, n);
    return __fmaf_rn(e2, r, q);
}

__device__ __forceinline__ const float* sel_anchor(int l,
    const float* a0, const float* a1, const float* a2, const float* a3, const float* a4) {
    switch (l) {
        case 0: return a0;
        case 1: return a1;
        case 2: return a2;
        case 3: return a3;
        default: return a4;
    }
}

__global__ __launch_bounds__(TPB) void main_kernel(
    const float* __restrict__ bb,   // (B, G, 4)
    const int*   __restrict__ ids,  // (B, G)
    const float* __restrict__ a0, const float* __restrict__ a1,
    const float* __restrict__ a2, const float* __restrict__ a3,
    const float* __restrict__ a4,
    float* __restrict__ out, LvlInfo L)
{
    __shared__ float4 sbox[NG];
    __shared__ float  sarea[NG], sid[NG];
    __shared__ int    s_last;
    // Fixup staging (used only by the last block; ~15.4 KB).
    __shared__ int    s_ag[NB * NG];
    __shared__ float  s_lab[NB * NG];
    __shared__ __align__(16) float4 s_reg[NB * NG];

    const int b    = blockIdx.y;
    const int tid  = threadIdx.x;
    const int lane = tid & 31;

    if (tid < NG) {
        float4 g4 = reinterpret_cast<const float4*>(bb)[b * NG + tid];
        sbox[tid]  = g4;
        sarea[tid] = __fmul_rn(g4.z - g4.x + 1.0f, g4.w - g4.y + 1.0f);
        sid[tid]   = (float)ids[b * NG + tid];
    }

    // Level of this block (blocks never span levels: 96/24/6/2/1).
    const int bx = blockIdx.x;
    int lvl = 0;
#pragma unroll
    for (int l = 1; l < NLVL; l++)
        if (bx >= L.boff[l]) lvl = l;

    const float* anch = sel_anchor(lvl, a0, a1, a2, a3, a4);
    const int nA = L.aoff[lvl + 1] - L.aoff[lvl];
    // ADJACENT pair: thread owns anchors base+0, base+1 => warp owns 64
    // consecutive anchors => tight warp bbox for pruning.
    const int base = ((bx - L.boff[lvl]) * TPB + tid) * APT;

    float4   av[APT];
    float    areaA[APT];
    unsigned lowb[APT];
    bool     act[APT];
    float    best[APT];
    int      bestg[APT];

    const float INF = __int_as_float(0x7F800000);
    float tx1 = INF, ty1 = INF, tx2 = -INF, ty2 = -INF;

#pragma unroll
    for (int k = 0; k < APT; k++) {
        int local = base + k;
        act[k] = local < nA;
        av[k]  = make_float4(4e9f, 4e9f, 4e9f, 4e9f);   // sentinel: never overlaps
        if (act[k]) {
            av[k] = reinterpret_cast<const float4*>(anch)[local];
            tx1 = fminf(tx1, av[k].x); ty1 = fminf(ty1, av[k].y);
            tx2 = fmaxf(tx2, av[k].z); ty2 = fmaxf(ty2, av[k].w);
        }
        areaA[k] = __fmul_rn(av[k].z - av[k].x + 1.0f, av[k].w - av[k].y + 1.0f);
        lowb[k]  = 0xFFFFFFFFu - (unsigned)local;
        best[k]  = 0.0f;   // zero-overlap rows => argmax g=0, matching jnp
        bestg[k] = 0;
    }

    // Warp bbox (xor pattern => all lanes hold the warp-wide result).
#pragma unroll
    for (int o = 16; o > 0; o >>= 1) {
        tx1 = fminf(tx1, __shfl_xor_sync(0xFFFFFFFFu, tx1, o));
        ty1 = fminf(ty1, __shfl_xor_sync(0xFFFFFFFFu, ty1, o));
        tx2 = fmaxf(tx2, __shfl_xor_sync(0xFFFFFFFFu, tx2, o));
        ty2 = fmaxf(ty2, __shfl_xor_sync(0xFFFFFFFFu, ty2, o));
    }
    // Conservative overlap bounds: GT can overlap some anchor in this warp only
    // if gb.z >= tx1-1 && gb.x <= tx2+1 && gb.w >= ty1-1 && gb.y <= ty2+1.
    // (+/-1 exact for coords < 2^23; all-inactive warps keep inf => never pass.)
    const float wx1 = tx1 - 1.0f, wx2 = tx2 + 1.0f;
    const float wy1 = ty1 - 1.0f, wy2 = ty2 + 1.0f;

    __syncthreads();

    // Ballot survival mask: lane g tests GT g (12 issues for all 20 GTs).
    unsigned mask;
    {
        bool surv = false;
        if (lane < NG) {
            float4 gb = sbox[lane];
            surv = (gb.z >= wx1) && (gb.x <= wx2) && (gb.w >= wy1) && (gb.y <= wy2);
        }
        mask = __ballot_sync(0xFFFFFFFFu, surv);
    }

    const unsigned long long gbase = (unsigned long long)(b * NLVL + lvl) * NG;

    // Iterate surviving GTs only, in ascending g (preserves first-wins ties).
    while (mask) {
        const int g = __ffs(mask) - 1;
        mask &= mask - 1;

        float4 gb  = sbox[g];
        float  sag = sarea[g];
        float    pv  = 0.0f;
        unsigned plo = 0u;
#pragma unroll
        for (int k = 0; k < APT; k++) {
            float iw = fminf(av[k].z, gb.z) - fmaxf(av[k].x, gb.x) + 1.0f;
            float ih = fminf(av[k].w, gb.w) - fmaxf(av[k].y, gb.y) + 1.0f;
            if (iw > 0.0f && ih > 0.0f) {
                float inter = __fmul_rn(iw, ih);
                float denom = __fsub_rn(__fadd_rn(areaA[k], sag), inter);
                float iou   = div_rn_fast(inter, denom);   // == IEEE rn div bits
                if (iou > best[k]) { best[k] = iou; bestg[k] = g; }
                // strict >: tie keeps k=0 (smaller idx) — matches u64-max.
                if (iou > pv) { pv = iou; plo = lowb[k]; }
            }
        }
        // Warp reduction via REDUX: max iou bits, then min idx among ties.
        unsigned hv = __float_as_uint(pv);
        unsigned mh = __reduce_max_sync(0xFFFFFFFFu, hv);
        if (mh != 0u) {   // warp-uniform
            unsigned lo = (hv == mh) ? plo : 0u;
            unsigned ml = __reduce_max_sync(0xFFFFFFFFu, lo);
            if (lane == 0)
                atomicMax(&g_gtpack[gbase + g],
                          ((unsigned long long)mh << 32) | (unsigned long long)ml);
        }
    }

    // Per-anchor outputs.
    const int Atot = L.aoff[NLVL];
    float* reg_base = out + (size_t)NB * Atot;
#pragma unroll
    for (int k = 0; k < APT; k++) {
        if (!act[k]) continue;
        const int aglob = L.aoff[lvl] + base + k;
        const bool pos    = best[k] >= 0.5f;
        const bool ignore = best[k] >= 0.4f;
        out[(size_t)b * Atot + aglob] = pos ? sid[bestg[k]] : (ignore ? -1.0f : 0.0f);

        float4 r = make_float4(0.f, 0.f, 0.f, 0.f);
        if (pos) {
            float4 gb = sbox[bestg[k]];
            float ew  = av[k].z - av[k].x + 1.0f;
            float eh  = av[k].w - av[k].y + 1.0f;
            float ecx = av[k].x + 0.5f * ew;
            float ecy = av[k].y + 0.5f * eh;
            float gw  = gb.z - gb.x + 1.0f;
            float gh  = gb.w - gb.y + 1.0f;
            float gcx = gb.x + 0.5f * gw;
            float gcy = gb.y + 0.5f * gh;
            r.x = div_rn_fast(gcx - ecx, ew);
            r.y = div_rn_fast(gcy - ecy, eh);
            r.z = logf(div_rn_fast(gw, ew));
            r.w = logf(div_rn_fast(gh, eh));
        }
        reinterpret_cast<float4*>(reg_base)[(size_t)b * Atot + aglob] = r;
    }

    // ── Last-block-done: final block applies forced positives ──
    __syncthreads();
    if (tid == 0) {
        __threadfence();
        int n = atomicAdd(&g_done, 1);
        s_last = (n == (int)(gridDim.x * gridDim.y) - 1);
    }
    __syncthreads();
    if (!s_last) return;
    __threadfence();

    for (int t = tid; t < NB * NG; t += TPB) {
        const int bb_i = t / NG, g = t % NG;

        // argmax over levels; strict >, ascending => first max wins
        // (bit-exact vs jnp.stack(...).argmax(axis=0)).
        float bestv = -1.0f;
        int bl = 0;
        unsigned long long bp = 0ull;
#pragma unroll
        for (int l = 0; l < NLVL; l++) {
            unsigned long long p = g_gtpack[(bb_i * NLVL + l) * NG + g];
            float v = __uint_as_float((unsigned)(p >> 32));
            if (v > bestv) { bestv = v; bl = l; bp = p; }
        }
        int local = (int)(0xFFFFFFFFu - (unsigned)(bp & 0xFFFFFFFFull));
        int aglob = L.aoff[bl] + local;

        const float* ap = sel_anchor(bl, a0, a1, a2, a3, a4) + (size_t)local * 4;
        float ax1 = ap[0], ay1 = ap[1], ax2 = ap[2], ay2 = ap[3];
        float4 gb = reinterpret_cast<const float4*>(bb)[bb_i * NG + g];

        float ew  = ax2 - ax1 + 1.0f;
        float eh  = ay2 - ay1 + 1.0f;
        float ecx = ax1 + 0.5f * ew;
        float ecy = ay1 + 0.5f * eh;
        float gw  = gb.z - gb.x + 1.0f;
        float gh  = gb.w - gb.y + 1.0f;
        float gcx = gb.x + 0.5f * gw;
        float gcy = gb.y + 0.5f * gh;
        float4 r;
        r.x = div_rn_fast(gcx - ecx, ew);
        r.y = div_rn_fast(gcy - ecy, eh);
        r.z = logf(div_rn_fast(gw, ew));
        r.w = logf(div_rn_fast(gh, eh));

        s_ag[t]  = aglob;
        s_lab[t] = (float)ids[bb_i * NG + g];
        s_reg[t] = r;
    }
    __syncthreads();

    if (tid < NB) {  // thread = batch; ascending g => deterministic last-wins
        for (int g = 0; g < NG; ++g) {
            int i = tid * NG + g;
            int aglob = s_ag[i];
            out[(size_t)tid * Atot + aglob] = s_lab[i];
            reinterpret_cast<float4*>(reg_base)[(size_t)tid * Atot + aglob] = s_reg[i];
        }
    }

    // Reset scratch for the next launch / graph replay.
    if (tid == 0) g_done = 0;
    for (int i = tid; i < NB * NLVL * NG; i += TPB)
        g_gtpack[i] = 0ull;
}

extern "C" void kernel_launch(void* const* d_in, const int* in_sizes, int n_in,
                              void* d_out, int out_size) {
    const float* bb  = (const float*)d_in[0];
    const int*   ids = (const int*)d_in[1];
    const float* A[NLVL];
    LvlInfo L;
    L.aoff[0] = 0;
    L.boff[0] = 0;
    for (int l = 0; l < NLVL; l++) {
        A[l] = (const float*)d_in[2 + l];
        int nA = in_sizes[2 + l] / 4;
        L.aoff[l + 1] = L.aoff[l] + nA;
        L.boff[l + 1] = L.boff[l] + (nA + TPB * APT - 1) / (TPB * APT);
    }
    float* out = (float*)d_out;

    dim3 grid(L.boff[NLVL], NB);
    main_kernel<<<grid, TPB>>>(bb, ids, A[0], A[1], A[2], A[3], A[4], out, L);
}